// round 13
// baseline (speedup 1.0000x reference)
#include <cuda_runtime.h>
#include <cuda_fp16.h>
#include <cstdint>
#include <math.h>

#define NN  50000
#define EE  1600000
#define NB  ((NN + 255) / 256)

// ---------------- scratch (device globals; no allocation) ----------------
__device__ __half g_xs [NN * 256];   // x split  [hi(128) | lo(128)]
__device__ __half g_hs [NN * 256];   // h split  [hi | lo]
__device__ __half g_zs [NN * 128];   // z split  [hi(64) | lo(64)]
__device__ __half g_xw16[NN * 128];  // fp16 gathered features (xw, then hw)
__device__ float  g_uv[NN * 128];    // [u | v] per node (fp32, decode input)
__device__ float  g_dinv[NN];
__device__ int    g_deg[NN];
__device__ int    g_rowptr[NN + 1];
__device__ int    g_cursor[NN];
__device__ int    g_col[EE];
__device__ int    g_partial[256];
__device__ __half g_wc1c[384 * 128]; // [Wc1hi; Wc1hi; Wc1lo]
__device__ __half g_wc2c[384 * 64];
__device__ __half g_wuvc[192 * 128]; // packed [W1top|W1bot] split-cat

// ---------------- CSR build ----------------
__global__ void hist_kernel(const int* __restrict__ dst, int E) {
    int i = blockIdx.x * blockDim.x + threadIdx.x;
    int E4 = E >> 2;
    if (i < E4) {
        int4 d = ((const int4*)dst)[i];
        atomicAdd(&g_deg[d.x], 1);
        atomicAdd(&g_deg[d.y], 1);
        atomicAdd(&g_deg[d.z], 1);
        atomicAdd(&g_deg[d.w], 1);
    }
    if (i == 0) {
        for (int r = E & ~3; r < E; r++) atomicAdd(&g_deg[dst[r]], 1);
    }
}

__global__ void scan_partial_kernel() {
    __shared__ int ws[8];
    int i = blockIdx.x * 256 + threadIdx.x;
    int t = threadIdx.x;
    int v = (i < NN) ? g_deg[i] : 0;
#pragma unroll
    for (int o = 16; o; o >>= 1) v += __shfl_xor_sync(0xffffffffu, v, o);
    if ((t & 31) == 0) ws[t >> 5] = v;
    __syncthreads();
    if (t < 8) {
        int s = ws[t];
#pragma unroll
        for (int o = 4; o; o >>= 1) s += __shfl_xor_sync(0xffu, s, o);
        if (t == 0) g_partial[blockIdx.x] = s;
    }
}

__global__ void scan_offsets_kernel(int E) {
    __shared__ int sm[256];
    int t = threadIdx.x;
    int v = (t < NB) ? g_partial[t] : 0;
    sm[t] = v;
    __syncthreads();
#pragma unroll
    for (int off = 1; off < 256; off <<= 1) {
        int a = (t >= off) ? sm[t - off] : 0;
        __syncthreads();
        sm[t] += a;
        __syncthreads();
    }
    if (t < NB) g_partial[t] = sm[t] - v;
    if (t == 0) g_rowptr[NN] = E;
}

__global__ void scan_final_kernel() {
    __shared__ int sm[256];
    int i = blockIdx.x * 256 + threadIdx.x;
    int t = threadIdx.x;
    int v = (i < NN) ? g_deg[i] : 0;
    sm[t] = v;
    __syncthreads();
#pragma unroll
    for (int off = 1; off < 256; off <<= 1) {
        int a = (t >= off) ? sm[t - off] : 0;
        __syncthreads();
        sm[t] += a;
        __syncthreads();
    }
    if (i < NN) {
        int excl = g_partial[blockIdx.x] + sm[t] - v;
        g_rowptr[i] = excl;
        g_cursor[i] = excl;
        g_dinv[i]   = rsqrtf((float)v + 1.0f);
    }
}

__global__ void fill_kernel(const int* __restrict__ src,
                            const int* __restrict__ dst, int E) {
    int i = blockIdx.x * blockDim.x + threadIdx.x;
    int E4 = E >> 2;
    if (i < E4) {
        int4 s4 = ((const int4*)src)[i];
        int4 d4 = ((const int4*)dst)[i];
        int p0 = atomicAdd(&g_cursor[d4.x], 1);
        int p1 = atomicAdd(&g_cursor[d4.y], 1);
        int p2 = atomicAdd(&g_cursor[d4.z], 1);
        int p3 = atomicAdd(&g_cursor[d4.w], 1);
        g_col[p0] = s4.x;
        g_col[p1] = s4.y;
        g_col[p2] = s4.z;
        g_col[p3] = s4.w;
    }
    if (i == 0) {
        for (int r = E & ~3; r < E; r++) {
            int pos = atomicAdd(&g_cursor[dst[r]], 1);
            g_col[pos] = src[r];
        }
    }
}

// ---------------- split/cat prep ----------------
__global__ void split_x_kernel(const float* __restrict__ x) {
    int i = blockIdx.x * blockDim.x + threadIdx.x;
    if (i >= NN * 32) return;
    float4 v = ((const float4*)x)[i];
    int node = i >> 5, q = (i & 31) * 4;
    __half2 h01 = __floats2half2_rn(v.x, v.y);
    __half2 h23 = __floats2half2_rn(v.z, v.w);
    float2 f01 = __half22float2(h01);
    float2 f23 = __half22float2(h23);
    __half2 l01 = __floats2half2_rn(v.x - f01.x, v.y - f01.y);
    __half2 l23 = __floats2half2_rn(v.z - f23.x, v.w - f23.y);
    __half2* hp = (__half2*)(g_xs + (size_t)node * 256 + q);
    hp[0] = h01; hp[1] = h23;
    __half2* lp = (__half2*)(g_xs + (size_t)node * 256 + 128 + q);
    lp[0] = l01; lp[1] = l23;
}

// all three weight cats in one kernel (960 blocks x 128 thr)
__global__ void build_weights_kernel(const float* __restrict__ Wc1,
                                     const float* __restrict__ Wc2,
                                     const float* __restrict__ W1) {
    int bid = blockIdx.x, j = threadIdx.x;
    if (bid < 384) {              // wc1c [384 x 128]
        int r = bid;
        int k = (r < 128) ? r : ((r < 256) ? r - 128 : r - 256);
        float w = Wc1[k * 128 + j];
        __half h = __float2half_rn(w);
        g_wc1c[r * 128 + j] = (r < 256) ? h : __float2half_rn(w - __half2float(h));
    } else if (bid < 768) {       // wc2c [384 x 64]
        if (j < 64) {
            int r = bid - 384;
            int k = (r < 128) ? r : ((r < 256) ? r - 128 : r - 256);
            float w = Wc2[k * 64 + j];
            __half h = __float2half_rn(w);
            g_wc2c[r * 64 + j] = (r < 256) ? h : __float2half_rn(w - __half2float(h));
        }
    } else {                      // wuvc [192 x 128]
        int r = bid - 768;
        int k = (r < 64) ? r : ((r < 128) ? r - 64 : r - 128);
        float w = (j < 64) ? W1[k * 64 + j] : W1[(64 + k) * 64 + (j - 64)];
        __half h = __float2half_rn(w);
        g_wuvc[r * 128 + j] = (r < 128) ? h : __float2half_rn(w - __half2float(h));
    }
}

// ---------------- TC GEMM (cp.async 2-stage pipelined) --------------------
// C[M,N] = (Ahi+Alo) @ W via K'=3K fp16 mma. A:[M,2K] halves; B:[3K,N].
__device__ __forceinline__ void ldm4(unsigned int* a, unsigned int addr) {
    asm volatile("ldmatrix.sync.aligned.m8n8.x4.shared.b16 {%0,%1,%2,%3}, [%4];"
                 : "=r"(a[0]), "=r"(a[1]), "=r"(a[2]), "=r"(a[3]) : "r"(addr));
}
__device__ __forceinline__ void ldm4t(unsigned int* b, unsigned int addr) {
    asm volatile("ldmatrix.sync.aligned.m8n8.x4.trans.shared.b16 {%0,%1,%2,%3}, [%4];"
                 : "=r"(b[0]), "=r"(b[1]), "=r"(b[2]), "=r"(b[3]) : "r"(addr));
}
__device__ __forceinline__ void mma16816(float* d, const unsigned int* a, const unsigned int* b) {
    asm volatile("mma.sync.aligned.m16n8k16.row.col.f32.f16.f16.f32 "
                 "{%0,%1,%2,%3}, {%4,%5,%6,%7}, {%8,%9}, {%0,%1,%2,%3};"
                 : "+f"(d[0]), "+f"(d[1]), "+f"(d[2]), "+f"(d[3])
                 : "r"(a[0]), "r"(a[1]), "r"(a[2]), "r"(a[3]), "r"(b[0]), "r"(b[1]));
}

#define TC_SMEM_BYTES ((2 * 128 * 72 + 2 * 64 * 72) * 2)   // 55296

template <bool HALF_OUT>
__global__ __launch_bounds__(256)
void tcgemm_kernel(const __half* __restrict__ A, const __half* __restrict__ B,
                   void* __restrict__ Cv, int M, int N, int K) {
    extern __shared__ __half smp[];
    const int ASZ = 128 * 72;        // halves per A stage
    const int BSZ = 64 * 72;
    __half* As = smp;                // [2][ASZ]
    __half* Bs = smp + 2 * ASZ;      // [2][BSZ]

    int t = threadIdx.x;
    int bm = blockIdx.y * 128;
    int bn = blockIdx.x * 64;
    int warp = t >> 5, lane = t & 31;
    int wr = warp & 3, wc = warp >> 2;
    int strideA = 2 * K;
    int nChunks = (3 * K) / 64;

    unsigned int asb = (unsigned int)__cvta_generic_to_shared(As);
    unsigned int bsb = (unsigned int)__cvta_generic_to_shared(Bs);

    // load mapping: A 2 thr/row (64B each), B 4 thr/row (32B each)
    int ar = t >> 1, ah = t & 1;
    int brw = t >> 2, bq = t & 3;
    int arow = bm + ar; if (arow >= M) arow = M - 1;   // clamp (extra rows give garbage C rows, never stored)

    auto prefetch = [&](int c, int st) {
        int L = c * 64;
        int srcA = (L < 2 * K) ? L : L - 2 * K;
        const __half* asrc = A + (size_t)arow * strideA + srcA + ah * 32;
        unsigned int adst = asb + (unsigned int)(st * ASZ * 2 + (ar * 72 + ah * 32) * 2);
#pragma unroll
        for (int j = 0; j < 4; j++)
            asm volatile("cp.async.ca.shared.global [%0], [%1], 16;"
                         :: "r"(adst + j * 16u), "l"(asrc + j * 8));
        const __half* bsrc = B + (size_t)(L + brw) * N + bn + bq * 16;
        unsigned int bdst = bsb + (unsigned int)(st * BSZ * 2 + (brw * 72 + bq * 16) * 2);
#pragma unroll
        for (int j = 0; j < 2; j++)
            asm volatile("cp.async.ca.shared.global [%0], [%1], 16;"
                         :: "r"(bdst + j * 16u), "l"(bsrc + j * 8));
        asm volatile("cp.async.commit_group;");
    };

    float acc[2][4][4] = {};

    prefetch(0, 0);
    for (int c = 0; c < nChunks; c++) {
        int st = c & 1;
        if (c + 1 < nChunks) {
            prefetch(c + 1, (c + 1) & 1);
            asm volatile("cp.async.wait_group 1;");
        } else {
            asm volatile("cp.async.wait_group 0;");
        }
        __syncthreads();
        unsigned int aB = asb + (unsigned int)(st * ASZ * 2);
        unsigned int bB = bsb + (unsigned int)(st * BSZ * 2);
#pragma unroll
        for (int kk = 0; kk < 4; kk++) {
            unsigned int a[2][4], b[2][4];
#pragma unroll
            for (int i = 0; i < 2; i++) {
                int row = wr * 32 + i * 16 + (lane & 15);
                ldm4(a[i], aB + (unsigned int)(row * 72 + kk * 16 + (lane >> 4) * 8) * 2u);
            }
#pragma unroll
            for (int g = 0; g < 2; g++) {
                int krow = kk * 16 + (lane & 15);
                ldm4t(b[g], bB + (unsigned int)(krow * 72 + wc * 32 + g * 16 + (lane >> 4) * 8) * 2u);
            }
#pragma unroll
            for (int i = 0; i < 2; i++)
#pragma unroll
                for (int j = 0; j < 4; j++)
                    mma16816(acc[i][j], a[i], &b[j >> 1][(j & 1) * 2]);
        }
        __syncthreads();
    }

    int lrow = lane >> 2, lcol = (lane & 3) * 2;
#pragma unroll
    for (int i = 0; i < 2; i++) {
#pragma unroll
        for (int j = 0; j < 4; j++) {
            int row = bm + wr * 32 + i * 16 + lrow;
            int col = bn + wc * 32 + j * 8 + lcol;
            if (HALF_OUT) {
                __half* C = (__half*)Cv;
                if (row < M)
                    *(__half2*)&C[(size_t)row * N + col] =
                        __floats2half2_rn(acc[i][j][0], acc[i][j][1]);
                if (row + 8 < M)
                    *(__half2*)&C[(size_t)(row + 8) * N + col] =
                        __floats2half2_rn(acc[i][j][2], acc[i][j][3]);
            } else {
                float* C = (float*)Cv;
                if (row < M)
                    *(float2*)&C[(size_t)row * N + col] =
                        make_float2(acc[i][j][0], acc[i][j][1]);
                if (row + 8 < M)
                    *(float2*)&C[(size_t)(row + 8) * N + col] =
                        make_float2(acc[i][j][2], acc[i][j][3]);
            }
        }
    }
}

// ---------------- GCN aggregation (fp16 gather, fp32 accum, split out) ----
__global__ void agg128_kernel(const __half* __restrict__ xw,
                              const float* __restrict__ bias) {
    int node = (blockIdx.x * blockDim.x + threadIdx.x) >> 5;
    int lane = threadIdx.x & 31;
    if (node >= NN) return;
    float di  = g_dinv[node];
    int   beg = g_rowptr[node], end = g_rowptr[node + 1];
    float4 acc = make_float4(0.f, 0.f, 0.f, 0.f);
    for (int base = beg; base < end; base += 32) {
        int m = end - base; if (m > 32) m = 32;
        int s = 0; float ds = 0.f;
        if (lane < m) { s = g_col[base + lane]; ds = g_dinv[s]; }
        int i = 0;
        for (; i + 8 <= m; i += 8) {
            int si[8]; float w[8]; uint2 xv[8];
#pragma unroll
            for (int j = 0; j < 8; j++) {
                si[j] = __shfl_sync(0xffffffffu, s,  i + j);
                w[j]  = __shfl_sync(0xffffffffu, ds, i + j);
            }
#pragma unroll
            for (int j = 0; j < 8; j++)
                xv[j] = *(const uint2*)(xw + (size_t)si[j] * 128 + lane * 4);
#pragma unroll
            for (int j = 0; j < 8; j++) {
                float2 lo = __half22float2(*(const __half2*)&xv[j].x);
                float2 hi = __half22float2(*(const __half2*)&xv[j].y);
                acc.x = fmaf(w[j], lo.x, acc.x);
                acc.y = fmaf(w[j], lo.y, acc.y);
                acc.z = fmaf(w[j], hi.x, acc.z);
                acc.w = fmaf(w[j], hi.y, acc.w);
            }
        }
        for (; i < m; i++) {
            int   si = __shfl_sync(0xffffffffu, s, i);
            float w  = __shfl_sync(0xffffffffu, ds, i);
            uint2 xv = *(const uint2*)(xw + (size_t)si * 128 + lane * 4);
            float2 lo = __half22float2(*(const __half2*)&xv.x);
            float2 hi = __half22float2(*(const __half2*)&xv.y);
            acc.x = fmaf(w, lo.x, acc.x); acc.y = fmaf(w, lo.y, acc.y);
            acc.z = fmaf(w, hi.x, acc.z); acc.w = fmaf(w, hi.y, acc.w);
        }
    }
    uint2 svp = *(const uint2*)(xw + (size_t)node * 128 + lane * 4);
    float2 slo = __half22float2(*(const __half2*)&svp.x);
    float2 shi = __half22float2(*(const __half2*)&svp.y);
    float4 b  = *(const float4*)(bias + lane * 4);
    float  d2 = di * di;
    float4 r;
    r.x = fmaxf(di * acc.x + d2 * slo.x + b.x, 0.f);
    r.y = fmaxf(di * acc.y + d2 * slo.y + b.y, 0.f);
    r.z = fmaxf(di * acc.z + d2 * shi.x + b.z, 0.f);
    r.w = fmaxf(di * acc.w + d2 * shi.y + b.w, 0.f);
    __half2 h01 = __floats2half2_rn(r.x, r.y);
    __half2 h23 = __floats2half2_rn(r.z, r.w);
    float2 f01 = __half22float2(h01), f23 = __half22float2(h23);
    __half2 l01 = __floats2half2_rn(r.x - f01.x, r.y - f01.y);
    __half2 l23 = __floats2half2_rn(r.z - f23.x, r.w - f23.y);
    __half2* hp = (__half2*)(g_hs + (size_t)node * 256 + lane * 4);
    hp[0] = h01; hp[1] = h23;
    __half2* lp = (__half2*)(g_hs + (size_t)node * 256 + 128 + lane * 4);
    lp[0] = l01; lp[1] = l23;
}

__global__ void agg64_kernel(const __half* __restrict__ xw,
                             const float* __restrict__ bias) {
    int node = (blockIdx.x * blockDim.x + threadIdx.x) >> 5;
    int lane = threadIdx.x & 31;
    if (node >= NN) return;
    float di  = g_dinv[node];
    int   beg = g_rowptr[node], end = g_rowptr[node + 1];
    float2 acc = make_float2(0.f, 0.f);
    for (int base = beg; base < end; base += 32) {
        int m = end - base; if (m > 32) m = 32;
        int s = 0; float ds = 0.f;
        if (lane < m) { s = g_col[base + lane]; ds = g_dinv[s]; }
        int i = 0;
        for (; i + 8 <= m; i += 8) {
            int si[8]; float w[8]; __half2 xv[8];
#pragma unroll
            for (int j = 0; j < 8; j++) {
                si[j] = __shfl_sync(0xffffffffu, s,  i + j);
                w[j]  = __shfl_sync(0xffffffffu, ds, i + j);
            }
#pragma unroll
            for (int j = 0; j < 8; j++)
                xv[j] = *(const __half2*)(xw + (size_t)si[j] * 64 + lane * 2);
#pragma unroll
            for (int j = 0; j < 8; j++) {
                float2 f = __half22float2(xv[j]);
                acc.x = fmaf(w[j], f.x, acc.x);
                acc.y = fmaf(w[j], f.y, acc.y);
            }
        }
        for (; i < m; i++) {
            int   si = __shfl_sync(0xffffffffu, s, i);
            float w  = __shfl_sync(0xffffffffu, ds, i);
            float2 f = __half22float2(*(const __half2*)(xw + (size_t)si * 64 + lane * 2));
            acc.x = fmaf(w, f.x, acc.x); acc.y = fmaf(w, f.y, acc.y);
        }
    }
    float2 sv = __half22float2(*(const __half2*)(xw + (size_t)node * 64 + lane * 2));
    float2 b  = *(const float2*)(bias + lane * 2);
    float  d2 = di * di;
    float rx = di * acc.x + d2 * sv.x + b.x;
    float ry = di * acc.y + d2 * sv.y + b.y;
    __half2 h = __floats2half2_rn(rx, ry);
    float2 f = __half22float2(h);
    __half2 l = __floats2half2_rn(rx - f.x, ry - f.y);
    *(__half2*)(g_zs + (size_t)node * 128 + lane * 2) = h;
    *(__half2*)(g_zs + (size_t)node * 128 + 64 + lane * 2) = l;
}

// ---------------- decode: warp per label edge (fp32 uv) ----------------
__global__ void decode_kernel(const float* __restrict__ uv,
                              const int* __restrict__ eli,
                              const float* __restrict__ b1,
                              const float* __restrict__ W2,
                              const float* __restrict__ b2,
                              float* __restrict__ out, int EL) {
    int e    = (blockIdx.x * blockDim.x + threadIdx.x) >> 5;
    int lane = threadIdx.x & 31;
    if (e >= EL) return;
    int s = eli[e];
    int d = eli[EL + e];
    const float2* ps = (const float2*)(uv + (size_t)s * 128);
    const float2* pd = (const float2*)(uv + (size_t)d * 128);
    float2 u_s = ps[lane];
    float2 v_s = ps[32 + lane];
    float2 u_d = pd[lane];
    float2 v_d = pd[32 + lane];
    float2 bb = ((const float2*)b1)[lane];
    float2 ww = ((const float2*)W2)[lane];
    float sum = 0.f, h;
    h = u_s.x + v_d.x + bb.x; sum = fmaf(fmaxf(h, 0.f), ww.x, sum);
    h = u_s.y + v_d.y + bb.y; sum = fmaf(fmaxf(h, 0.f), ww.y, sum);
    h = u_d.x + v_s.x + bb.x; sum = fmaf(fmaxf(h, 0.f), ww.x, sum);
    h = u_d.y + v_s.y + bb.y; sum = fmaf(fmaxf(h, 0.f), ww.y, sum);
#pragma unroll
    for (int o = 16; o; o >>= 1) sum += __shfl_xor_sync(0xffffffffu, sum, o);
    if (lane == 0) {
        float val = 0.5f * sum + b2[0];
        out[e]      = -val;
        out[EL + e] =  val;
    }
}

// ---------------- launch ----------------
extern "C" void kernel_launch(void* const* d_in, const int* in_sizes, int n_in,
                              void* d_out, int out_size) {
    const float* x   = (const float*)d_in[0];
    const int*   ei  = (const int*)d_in[1];
    const int*   eli = (const int*)d_in[2];
    const float* Wc1 = (const float*)d_in[3];
    const float* bc1 = (const float*)d_in[4];
    const float* Wc2 = (const float*)d_in[5];
    const float* bc2 = (const float*)d_in[6];
    const float* W1  = (const float*)d_in[7];
    const float* b1  = (const float*)d_in[8];
    const float* W2  = (const float*)d_in[9];
    const float* b2  = (const float*)d_in[10];
    float* out = (float*)d_out;

    int E  = in_sizes[1] / 2;
    int EL = in_sizes[2] / 2;

    void *p_xs, *p_hs, *p_zs, *p_xw16, *p_uv, *p_deg, *p_wc1c, *p_wc2c, *p_wuvc;
    cudaGetSymbolAddress(&p_xs,   g_xs);
    cudaGetSymbolAddress(&p_hs,   g_hs);
    cudaGetSymbolAddress(&p_zs,   g_zs);
    cudaGetSymbolAddress(&p_xw16, g_xw16);
    cudaGetSymbolAddress(&p_uv,   g_uv);
    cudaGetSymbolAddress(&p_deg,  g_deg);
    cudaGetSymbolAddress(&p_wc1c, g_wc1c);
    cudaGetSymbolAddress(&p_wc2c, g_wc2c);
    cudaGetSymbolAddress(&p_wuvc, g_wuvc);

    static cudaStream_t s1 = nullptr;
    static cudaEvent_t  evFork = nullptr, evJoin = nullptr;
    if (s1 == nullptr) {
        cudaStreamCreateWithFlags(&s1, cudaStreamNonBlocking);
        cudaEventCreateWithFlags(&evFork, cudaEventDisableTiming);
        cudaEventCreateWithFlags(&evJoin, cudaEventDisableTiming);
        cudaFuncSetAttribute(tcgemm_kernel<true>,
                             cudaFuncAttributeMaxDynamicSharedMemorySize, TC_SMEM_BYTES);
        cudaFuncSetAttribute(tcgemm_kernel<false>,
                             cudaFuncAttributeMaxDynamicSharedMemorySize, TC_SMEM_BYTES);
    }

    int gy = (NN + 127) / 128;   // 391
    int E4 = E >> 2;

    // ---- fork: CSR chain on s1 ----
    cudaEventRecord(evFork, 0);
    cudaStreamWaitEvent(s1, evFork, 0);
    cudaMemsetAsync(p_deg, 0, NN * sizeof(int), s1);
    hist_kernel<<<(E4 + 255) / 256, 256, 0, s1>>>(ei + E, E);
    scan_partial_kernel<<<NB, 256, 0, s1>>>();
    scan_offsets_kernel<<<1, 256, 0, s1>>>(E);
    scan_final_kernel<<<NB, 256, 0, s1>>>();
    fill_kernel<<<(E4 + 255) / 256, 256, 0, s1>>>(ei, ei + E, E);
    cudaEventRecord(evJoin, s1);

    // main stream (concurrent): prep + GEMM1
    split_x_kernel<<<(NN * 32 + 255) / 256, 256>>>(x);
    build_weights_kernel<<<960, 128>>>(Wc1, Wc2, W1);
    tcgemm_kernel<true><<<dim3(2, gy), 256, TC_SMEM_BYTES>>>(
        (const __half*)p_xs, (const __half*)p_wc1c, p_xw16, NN, 128, 128);

    // ---- join ----
    cudaStreamWaitEvent(0, evJoin, 0);

    agg128_kernel<<<(NN + 7) / 8, 256>>>((const __half*)p_xw16, bc1);
    tcgemm_kernel<true><<<dim3(1, gy), 256, TC_SMEM_BYTES>>>(
        (const __half*)p_hs, (const __half*)p_wc2c, p_xw16, NN, 64, 128);
    agg64_kernel<<<(NN + 7) / 8, 256>>>((const __half*)p_xw16, bc2);
    tcgemm_kernel<false><<<dim3(2, gy), 256, TC_SMEM_BYTES>>>(
        (const __half*)p_zs, (const __half*)p_wuvc, p_uv, NN, 128, 64);
    decode_kernel<<<(EL * 32 + 255) / 256, 256>>>((const float*)p_uv, eli, b1, W2, b2, out, EL);
}

// round 14
// speedup vs baseline: 1.0225x; 1.0225x over previous
#include <cuda_runtime.h>
#include <cuda_fp16.h>
#include <cstdint>
#include <math.h>

#define NN  50000
#define EE  1600000
#define NB  ((NN + 255) / 256)    // 196 scan segments
#define CSRB 296                  // persistent CSR blocks (2/SM, always resident)

// ---------------- scratch (device globals; no allocation) ----------------
__device__ __half g_xs [NN * 256];   // x split  [hi(128) | lo(128)]
__device__ __half g_hs [NN * 256];   // h split  [hi | lo]
__device__ __half g_zs [NN * 128];   // z split  [hi(64) | lo(64)]
__device__ __half g_xw16[NN * 128];  // fp16 gathered features (xw, then hw)
__device__ float  g_uv[NN * 128];    // [u | v] per node (fp32, decode input)
__device__ float  g_dinv[NN];
__device__ int    g_deg[NN];
__device__ int    g_rowptr[NN + 1];
__device__ int    g_cursor[NN];
__device__ int    g_col[EE];
__device__ int    g_partial[256];
__device__ volatile unsigned g_barc;   // grid-barrier arrival count (host-zeroed per launch)
__device__ __half g_wc1c[384 * 128]; // [Wc1hi; Wc1hi; Wc1lo]
__device__ __half g_wc2c[384 * 64];
__device__ __half g_wuvc[192 * 128]; // packed [W1top|W1bot] split-cat

// ---------------- fused CSR build (single persistent kernel) ----------------
__device__ __forceinline__ void gridbar(unsigned target) {
    __syncthreads();
    if (threadIdx.x == 0) {
        __threadfence();
        atomicAdd((unsigned*)&g_barc, 1u);
        while (g_barc < target) { }
    }
    __syncthreads();
}

__global__ __launch_bounds__(256)
void csr_fused_kernel(const int* __restrict__ src,
                      const int* __restrict__ dst, int E) {
    __shared__ int sm [256];
    __shared__ int sm2[256];
    const unsigned G = gridDim.x;
    int t   = threadIdx.x;
    int gid = blockIdx.x * 256 + t;
    int nth = gridDim.x * 256;
    int E4  = E >> 2;

    // phase 0: zero deg
    for (int i = gid; i < NN; i += nth) g_deg[i] = 0;
    gridbar(G);

    // phase 1: histogram (4 edges/thread, grid-stride)
    for (int i = gid; i < E4; i += nth) {
        int4 d = ((const int4*)dst)[i];
        atomicAdd(&g_deg[d.x], 1);
        atomicAdd(&g_deg[d.y], 1);
        atomicAdd(&g_deg[d.z], 1);
        atomicAdd(&g_deg[d.w], 1);
    }
    if (gid == 0)
        for (int r = E & ~3; r < E; r++) atomicAdd(&g_deg[dst[r]], 1);
    gridbar(2 * G);

    // phase 2a: per-segment inclusive scan (blocks 0..NB-1), keep in shared
    int myv = 0;
    if (blockIdx.x < NB) {
        int i = blockIdx.x * 256 + t;
        myv = (i < NN) ? g_deg[i] : 0;
        sm[t] = myv;
        __syncthreads();
#pragma unroll
        for (int off = 1; off < 256; off <<= 1) {
            int a = (t >= off) ? sm[t - off] : 0;
            __syncthreads();
            sm[t] += a;
            __syncthreads();
        }
        if (t == 255) g_partial[blockIdx.x] = sm[255];
    }
    gridbar(3 * G);

    // phase 2b: block 0 scans the NB partials -> exclusive offsets
    if (blockIdx.x == 0) {
        int v = (t < NB) ? g_partial[t] : 0;
        sm2[t] = v;
        __syncthreads();
#pragma unroll
        for (int off = 1; off < 256; off <<= 1) {
            int a = (t >= off) ? sm2[t - off] : 0;
            __syncthreads();
            sm2[t] += a;
            __syncthreads();
        }
        if (t < NB) g_partial[t] = sm2[t] - v;
        if (t == 0) g_rowptr[NN] = E;
    }
    gridbar(4 * G);

    // phase 2c: finalize rowptr/cursor/dinv (shared sm[] persisted)
    if (blockIdx.x < NB) {
        int i = blockIdx.x * 256 + t;
        if (i < NN) {
            int excl = g_partial[blockIdx.x] + sm[t] - myv;
            g_rowptr[i] = excl;
            g_cursor[i] = excl;
            g_dinv[i]   = rsqrtf((float)myv + 1.0f);
        }
    }
    gridbar(5 * G);

    // phase 3: fill (4 edges/thread, grid-stride)
    for (int i = gid; i < E4; i += nth) {
        int4 s4 = ((const int4*)src)[i];
        int4 d4 = ((const int4*)dst)[i];
        int p0 = atomicAdd(&g_cursor[d4.x], 1);
        int p1 = atomicAdd(&g_cursor[d4.y], 1);
        int p2 = atomicAdd(&g_cursor[d4.z], 1);
        int p3 = atomicAdd(&g_cursor[d4.w], 1);
        g_col[p0] = s4.x;
        g_col[p1] = s4.y;
        g_col[p2] = s4.z;
        g_col[p3] = s4.w;
    }
    if (gid == 0) {
        for (int r = E & ~3; r < E; r++) {
            int pos = atomicAdd(&g_cursor[dst[r]], 1);
            g_col[pos] = src[r];
        }
    }
}

// ---------------- split/cat prep ----------------
__global__ void split_x_kernel(const float* __restrict__ x) {
    int i = blockIdx.x * blockDim.x + threadIdx.x;
    if (i >= NN * 32) return;
    float4 v = ((const float4*)x)[i];
    int node = i >> 5, q = (i & 31) * 4;
    __half2 h01 = __floats2half2_rn(v.x, v.y);
    __half2 h23 = __floats2half2_rn(v.z, v.w);
    float2 f01 = __half22float2(h01);
    float2 f23 = __half22float2(h23);
    __half2 l01 = __floats2half2_rn(v.x - f01.x, v.y - f01.y);
    __half2 l23 = __floats2half2_rn(v.z - f23.x, v.w - f23.y);
    __half2* hp = (__half2*)(g_xs + (size_t)node * 256 + q);
    hp[0] = h01; hp[1] = h23;
    __half2* lp = (__half2*)(g_xs + (size_t)node * 256 + 128 + q);
    lp[0] = l01; lp[1] = l23;
}

__global__ void build_weights_kernel(const float* __restrict__ Wc1,
                                     const float* __restrict__ Wc2,
                                     const float* __restrict__ W1) {
    int bid = blockIdx.x, j = threadIdx.x;
    if (bid < 384) {
        int r = bid;
        int k = (r < 128) ? r : ((r < 256) ? r - 128 : r - 256);
        float w = Wc1[k * 128 + j];
        __half h = __float2half_rn(w);
        g_wc1c[r * 128 + j] = (r < 256) ? h : __float2half_rn(w - __half2float(h));
    } else if (bid < 768) {
        if (j < 64) {
            int r = bid - 384;
            int k = (r < 128) ? r : ((r < 256) ? r - 128 : r - 256);
            float w = Wc2[k * 64 + j];
            __half h = __float2half_rn(w);
            g_wc2c[r * 64 + j] = (r < 256) ? h : __float2half_rn(w - __half2float(h));
        }
    } else {
        int r = bid - 768;
        int k = (r < 64) ? r : ((r < 128) ? r - 64 : r - 128);
        float w = (j < 64) ? W1[k * 64 + j] : W1[(64 + k) * 64 + (j - 64)];
        __half h = __float2half_rn(w);
        g_wuvc[r * 128 + j] = (r < 128) ? h : __float2half_rn(w - __half2float(h));
    }
}

// ---------------- TC GEMM (cp.async 2-stage pipelined) --------------------
__device__ __forceinline__ void ldm4(unsigned int* a, unsigned int addr) {
    asm volatile("ldmatrix.sync.aligned.m8n8.x4.shared.b16 {%0,%1,%2,%3}, [%4];"
                 : "=r"(a[0]), "=r"(a[1]), "=r"(a[2]), "=r"(a[3]) : "r"(addr));
}
__device__ __forceinline__ void ldm4t(unsigned int* b, unsigned int addr) {
    asm volatile("ldmatrix.sync.aligned.m8n8.x4.trans.shared.b16 {%0,%1,%2,%3}, [%4];"
                 : "=r"(b[0]), "=r"(b[1]), "=r"(b[2]), "=r"(b[3]) : "r"(addr));
}
__device__ __forceinline__ void mma16816(float* d, const unsigned int* a, const unsigned int* b) {
    asm volatile("mma.sync.aligned.m16n8k16.row.col.f32.f16.f16.f32 "
                 "{%0,%1,%2,%3}, {%4,%5,%6,%7}, {%8,%9}, {%0,%1,%2,%3};"
                 : "+f"(d[0]), "+f"(d[1]), "+f"(d[2]), "+f"(d[3])
                 : "r"(a[0]), "r"(a[1]), "r"(a[2]), "r"(a[3]), "r"(b[0]), "r"(b[1]));
}

#define TC_SMEM_BYTES ((2 * 128 * 72 + 2 * 64 * 72) * 2)   // 55296

template <bool HALF_OUT>
__global__ __launch_bounds__(256)
void tcgemm_kernel(const __half* __restrict__ A, const __half* __restrict__ B,
                   void* __restrict__ Cv, int M, int N, int K) {
    extern __shared__ __half smp[];
    const int ASZ = 128 * 72;
    const int BSZ = 64 * 72;
    __half* As = smp;
    __half* Bs = smp + 2 * ASZ;

    int t = threadIdx.x;
    int bm = blockIdx.y * 128;
    int bn = blockIdx.x * 64;
    int warp = t >> 5, lane = t & 31;
    int wr = warp & 3, wc = warp >> 2;
    int strideA = 2 * K;
    int nChunks = (3 * K) / 64;

    unsigned int asb = (unsigned int)__cvta_generic_to_shared(As);
    unsigned int bsb = (unsigned int)__cvta_generic_to_shared(Bs);

    int ar = t >> 1, ah = t & 1;
    int brw = t >> 2, bq = t & 3;
    int arow = bm + ar; if (arow >= M) arow = M - 1;

    auto prefetch = [&](int c, int st) {
        int L = c * 64;
        int srcA = (L < 2 * K) ? L : L - 2 * K;
        const __half* asrc = A + (size_t)arow * strideA + srcA + ah * 32;
        unsigned int adst = asb + (unsigned int)(st * ASZ * 2 + (ar * 72 + ah * 32) * 2);
#pragma unroll
        for (int j = 0; j < 4; j++)
            asm volatile("cp.async.ca.shared.global [%0], [%1], 16;"
                         :: "r"(adst + j * 16u), "l"(asrc + j * 8));
        const __half* bsrc = B + (size_t)(L + brw) * N + bn + bq * 16;
        unsigned int bdst = bsb + (unsigned int)(st * BSZ * 2 + (brw * 72 + bq * 16) * 2);
#pragma unroll
        for (int j = 0; j < 2; j++)
            asm volatile("cp.async.ca.shared.global [%0], [%1], 16;"
                         :: "r"(bdst + j * 16u), "l"(bsrc + j * 8));
        asm volatile("cp.async.commit_group;");
    };

    float acc[2][4][4] = {};

    prefetch(0, 0);
    for (int c = 0; c < nChunks; c++) {
        int st = c & 1;
        if (c + 1 < nChunks) {
            prefetch(c + 1, (c + 1) & 1);
            asm volatile("cp.async.wait_group 1;");
        } else {
            asm volatile("cp.async.wait_group 0;");
        }
        __syncthreads();
        unsigned int aB = asb + (unsigned int)(st * ASZ * 2);
        unsigned int bB = bsb + (unsigned int)(st * BSZ * 2);
#pragma unroll
        for (int kk = 0; kk < 4; kk++) {
            unsigned int a[2][4], b[2][4];
#pragma unroll
            for (int i = 0; i < 2; i++) {
                int row = wr * 32 + i * 16 + (lane & 15);
                ldm4(a[i], aB + (unsigned int)(row * 72 + kk * 16 + (lane >> 4) * 8) * 2u);
            }
#pragma unroll
            for (int g = 0; g < 2; g++) {
                int krow = kk * 16 + (lane & 15);
                ldm4t(b[g], bB + (unsigned int)(krow * 72 + wc * 32 + g * 16 + (lane >> 4) * 8) * 2u);
            }
#pragma unroll
            for (int i = 0; i < 2; i++)
#pragma unroll
                for (int j = 0; j < 4; j++)
                    mma16816(acc[i][j], a[i], &b[j >> 1][(j & 1) * 2]);
        }
        __syncthreads();
    }

    int lrow = lane >> 2, lcol = (lane & 3) * 2;
#pragma unroll
    for (int i = 0; i < 2; i++) {
#pragma unroll
        for (int j = 0; j < 4; j++) {
            int row = bm + wr * 32 + i * 16 + lrow;
            int col = bn + wc * 32 + j * 8 + lcol;
            if (HALF_OUT) {
                __half* C = (__half*)Cv;
                if (row < M)
                    *(__half2*)&C[(size_t)row * N + col] =
                        __floats2half2_rn(acc[i][j][0], acc[i][j][1]);
                if (row + 8 < M)
                    *(__half2*)&C[(size_t)(row + 8) * N + col] =
                        __floats2half2_rn(acc[i][j][2], acc[i][j][3]);
            } else {
                float* C = (float*)Cv;
                if (row < M)
                    *(float2*)&C[(size_t)row * N + col] =
                        make_float2(acc[i][j][0], acc[i][j][1]);
                if (row + 8 < M)
                    *(float2*)&C[(size_t)(row + 8) * N + col] =
                        make_float2(acc[i][j][2], acc[i][j][3]);
            }
        }
    }
}

// ---------------- GCN aggregation (fp16 gather, fp32 accum, split out) ----
__global__ void agg128_kernel(const __half* __restrict__ xw,
                              const float* __restrict__ bias) {
    int node = (blockIdx.x * blockDim.x + threadIdx.x) >> 5;
    int lane = threadIdx.x & 31;
    if (node >= NN) return;
    float di  = g_dinv[node];
    int   beg = g_rowptr[node], end = g_rowptr[node + 1];
    float4 acc = make_float4(0.f, 0.f, 0.f, 0.f);
    for (int base = beg; base < end; base += 32) {
        int m = end - base; if (m > 32) m = 32;
        int s = 0; float ds = 0.f;
        if (lane < m) { s = g_col[base + lane]; ds = g_dinv[s]; }
        int i = 0;
        for (; i + 8 <= m; i += 8) {
            int si[8]; float w[8]; uint2 xv[8];
#pragma unroll
            for (int j = 0; j < 8; j++) {
                si[j] = __shfl_sync(0xffffffffu, s,  i + j);
                w[j]  = __shfl_sync(0xffffffffu, ds, i + j);
            }
#pragma unroll
            for (int j = 0; j < 8; j++)
                xv[j] = *(const uint2*)(xw + (size_t)si[j] * 128 + lane * 4);
#pragma unroll
            for (int j = 0; j < 8; j++) {
                float2 lo = __half22float2(*(const __half2*)&xv[j].x);
                float2 hi = __half22float2(*(const __half2*)&xv[j].y);
                acc.x = fmaf(w[j], lo.x, acc.x);
                acc.y = fmaf(w[j], lo.y, acc.y);
                acc.z = fmaf(w[j], hi.x, acc.z);
                acc.w = fmaf(w[j], hi.y, acc.w);
            }
        }
        for (; i < m; i++) {
            int   si = __shfl_sync(0xffffffffu, s, i);
            float w  = __shfl_sync(0xffffffffu, ds, i);
            uint2 xv = *(const uint2*)(xw + (size_t)si * 128 + lane * 4);
            float2 lo = __half22float2(*(const __half2*)&xv.x);
            float2 hi = __half22float2(*(const __half2*)&xv.y);
            acc.x = fmaf(w, lo.x, acc.x); acc.y = fmaf(w, lo.y, acc.y);
            acc.z = fmaf(w, hi.x, acc.z); acc.w = fmaf(w, hi.y, acc.w);
        }
    }
    uint2 svp = *(const uint2*)(xw + (size_t)node * 128 + lane * 4);
    float2 slo = __half22float2(*(const __half2*)&svp.x);
    float2 shi = __half22float2(*(const __half2*)&svp.y);
    float4 b  = *(const float4*)(bias + lane * 4);
    float  d2 = di * di;
    float4 r;
    r.x = fmaxf(di * acc.x + d2 * slo.x + b.x, 0.f);
    r.y = fmaxf(di * acc.y + d2 * slo.y + b.y, 0.f);
    r.z = fmaxf(di * acc.z + d2 * shi.x + b.z, 0.f);
    r.w = fmaxf(di * acc.w + d2 * shi.y + b.w, 0.f);
    __half2 h01 = __floats2half2_rn(r.x, r.y);
    __half2 h23 = __floats2half2_rn(r.z, r.w);
    float2 f01 = __half22float2(h01), f23 = __half22float2(h23);
    __half2 l01 = __floats2half2_rn(r.x - f01.x, r.y - f01.y);
    __half2 l23 = __floats2half2_rn(r.z - f23.x, r.w - f23.y);
    __half2* hp = (__half2*)(g_hs + (size_t)node * 256 + lane * 4);
    hp[0] = h01; hp[1] = h23;
    __half2* lp = (__half2*)(g_hs + (size_t)node * 256 + 128 + lane * 4);
    lp[0] = l01; lp[1] = l23;
}

__global__ void agg64_kernel(const __half* __restrict__ xw,
                             const float* __restrict__ bias) {
    int node = (blockIdx.x * blockDim.x + threadIdx.x) >> 5;
    int lane = threadIdx.x & 31;
    if (node >= NN) return;
    float di  = g_dinv[node];
    int   beg = g_rowptr[node], end = g_rowptr[node + 1];
    float2 acc = make_float2(0.f, 0.f);
    for (int base = beg; base < end; base += 32) {
        int m = end - base; if (m > 32) m = 32;
        int s = 0; float ds = 0.f;
        if (lane < m) { s = g_col[base + lane]; ds = g_dinv[s]; }
        int i = 0;
        for (; i + 8 <= m; i += 8) {
            int si[8]; float w[8]; __half2 xv[8];
#pragma unroll
            for (int j = 0; j < 8; j++) {
                si[j] = __shfl_sync(0xffffffffu, s,  i + j);
                w[j]  = __shfl_sync(0xffffffffu, ds, i + j);
            }
#pragma unroll
            for (int j = 0; j < 8; j++)
                xv[j] = *(const __half2*)(xw + (size_t)si[j] * 64 + lane * 2);
#pragma unroll
            for (int j = 0; j < 8; j++) {
                float2 f = __half22float2(xv[j]);
                acc.x = fmaf(w[j], f.x, acc.x);
                acc.y = fmaf(w[j], f.y, acc.y);
            }
        }
        for (; i < m; i++) {
            int   si = __shfl_sync(0xffffffffu, s, i);
            float w  = __shfl_sync(0xffffffffu, ds, i);
            float2 f = __half22float2(*(const __half2*)(xw + (size_t)si * 64 + lane * 2));
            acc.x = fmaf(w, f.x, acc.x); acc.y = fmaf(w, f.y, acc.y);
        }
    }
    float2 sv = __half22float2(*(const __half2*)(xw + (size_t)node * 64 + lane * 2));
    float2 b  = *(const float2*)(bias + lane * 2);
    float  d2 = di * di;
    float rx = di * acc.x + d2 * sv.x + b.x;
    float ry = di * acc.y + d2 * sv.y + b.y;
    __half2 h = __floats2half2_rn(rx, ry);
    float2 f = __half22float2(h);
    __half2 l = __floats2half2_rn(rx - f.x, ry - f.y);
    *(__half2*)(g_zs + (size_t)node * 128 + lane * 2) = h;
    *(__half2*)(g_zs + (size_t)node * 128 + 64 + lane * 2) = l;
}

// ---------------- decode: warp per label edge (fp32 uv) ----------------
__global__ void decode_kernel(const float* __restrict__ uv,
                              const int* __restrict__ eli,
                              const float* __restrict__ b1,
                              const float* __restrict__ W2,
                              const float* __restrict__ b2,
                              float* __restrict__ out, int EL) {
    int e    = (blockIdx.x * blockDim.x + threadIdx.x) >> 5;
    int lane = threadIdx.x & 31;
    if (e >= EL) return;
    int s = eli[e];
    int d = eli[EL + e];
    const float2* ps = (const float2*)(uv + (size_t)s * 128);
    const float2* pd = (const float2*)(uv + (size_t)d * 128);
    float2 u_s = ps[lane];
    float2 v_s = ps[32 + lane];
    float2 u_d = pd[lane];
    float2 v_d = pd[32 + lane];
    float2 bb = ((const float2*)b1)[lane];
    float2 ww = ((const float2*)W2)[lane];
    float sum = 0.f, h;
    h = u_s.x + v_d.x + bb.x; sum = fmaf(fmaxf(h, 0.f), ww.x, sum);
    h = u_s.y + v_d.y + bb.y; sum = fmaf(fmaxf(h, 0.f), ww.y, sum);
    h = u_d.x + v_s.x + bb.x; sum = fmaf(fmaxf(h, 0.f), ww.x, sum);
    h = u_d.y + v_s.y + bb.y; sum = fmaf(fmaxf(h, 0.f), ww.y, sum);
#pragma unroll
    for (int o = 16; o; o >>= 1) sum += __shfl_xor_sync(0xffffffffu, sum, o);
    if (lane == 0) {
        float val = 0.5f * sum + b2[0];
        out[e]      = -val;
        out[EL + e] =  val;
    }
}

// ---------------- launch ----------------
extern "C" void kernel_launch(void* const* d_in, const int* in_sizes, int n_in,
                              void* d_out, int out_size) {
    const float* x   = (const float*)d_in[0];
    const int*   ei  = (const int*)d_in[1];
    const int*   eli = (const int*)d_in[2];
    const float* Wc1 = (const float*)d_in[3];
    const float* bc1 = (const float*)d_in[4];
    const float* Wc2 = (const float*)d_in[5];
    const float* bc2 = (const float*)d_in[6];
    const float* W1  = (const float*)d_in[7];
    const float* b1  = (const float*)d_in[8];
    const float* W2  = (const float*)d_in[9];
    const float* b2  = (const float*)d_in[10];
    float* out = (float*)d_out;

    int E  = in_sizes[1] / 2;
    int EL = in_sizes[2] / 2;

    void *p_xs, *p_hs, *p_zs, *p_xw16, *p_uv, *p_barc, *p_wc1c, *p_wc2c, *p_wuvc;
    cudaGetSymbolAddress(&p_xs,   g_xs);
    cudaGetSymbolAddress(&p_hs,   g_hs);
    cudaGetSymbolAddress(&p_zs,   g_zs);
    cudaGetSymbolAddress(&p_xw16, g_xw16);
    cudaGetSymbolAddress(&p_uv,   g_uv);
    cudaGetSymbolAddress(&p_barc, *(unsigned(*)[1])&g_barc);
    cudaGetSymbolAddress(&p_wc1c, g_wc1c);
    cudaGetSymbolAddress(&p_wc2c, g_wc2c);
    cudaGetSymbolAddress(&p_wuvc, g_wuvc);

    static cudaStream_t s1 = nullptr;
    static cudaEvent_t  evFork = nullptr, evJoin = nullptr;
    if (s1 == nullptr) {
        cudaStreamCreateWithFlags(&s1, cudaStreamNonBlocking);
        cudaEventCreateWithFlags(&evFork, cudaEventDisableTiming);
        cudaEventCreateWithFlags(&evJoin, cudaEventDisableTiming);
        cudaFuncSetAttribute(tcgemm_kernel<true>,
                             cudaFuncAttributeMaxDynamicSharedMemorySize, TC_SMEM_BYTES);
        cudaFuncSetAttribute(tcgemm_kernel<false>,
                             cudaFuncAttributeMaxDynamicSharedMemorySize, TC_SMEM_BYTES);
    }

    int gy = (NN + 127) / 128;   // 391

    // ---- fork: fused CSR on s1 ----
    cudaEventRecord(evFork, 0);
    cudaStreamWaitEvent(s1, evFork, 0);
    cudaMemsetAsync(p_barc, 0, sizeof(unsigned), s1);
    csr_fused_kernel<<<CSRB, 256, 0, s1>>>(ei, ei + E, E);
    cudaEventRecord(evJoin, s1);

    // main stream (concurrent): prep + GEMM1
    split_x_kernel<<<(NN * 32 + 255) / 256, 256>>>(x);
    build_weights_kernel<<<960, 128>>>(Wc1, Wc2, W1);
    tcgemm_kernel<true><<<dim3(2, gy), 256, TC_SMEM_BYTES>>>(
        (const __half*)p_xs, (const __half*)p_wc1c, p_xw16, NN, 128, 128);

    // ---- join ----
    cudaStreamWaitEvent(0, evJoin, 0);

    agg128_kernel<<<(NN + 7) / 8, 256>>>((const __half*)p_xw16, bc1);
    tcgemm_kernel<true><<<dim3(1, gy), 256, TC_SMEM_BYTES>>>(
        (const __half*)p_hs, (const __half*)p_wc2c, p_xw16, NN, 64, 128);
    agg64_kernel<<<(NN + 7) / 8, 256>>>((const __half*)p_xw16, bc2);
    tcgemm_kernel<false><<<dim3(2, gy), 256, TC_SMEM_BYTES>>>(
        (const __half*)p_zs, (const __half*)p_wuvc, p_uv, NN, 128, 64);
    decode_kernel<<<(EL * 32 + 255) / 256, 256>>>((const float*)p_uv, eli, b1, W2, b2, out, EL);
}